// round 3
// baseline (speedup 1.0000x reference)
#include <cuda_runtime.h>
#include <cuda_bf16.h>
#include <math.h>

// AssociativeLIF forward:
//  T=8, B=128, D=8192, NC=64, per_cluster=128
//  outputs: ss [T,B,D] then vt [T,B,D] concatenated into d_out (float32)

#define T_STEPS 8
#define BATCH   128
#define DIM     8192
#define NC      64
#define TPB     1024
#define NPT     (DIM / TPB)      // 8 neurons per thread
#define NGRP    (TPB / NC)       // 16 thread-groups for partial reduction
#define V_RESET (-0.1f)
#define REF_T   2

__global__ __launch_bounds__(TPB, 1)
void assoc_lif_kernel(const float* __restrict__ x,        // [T,B,D]
                      const float* __restrict__ th_raw,   // [D]
                      const float* __restrict__ bm_raw,   // [1]
                      const float* __restrict__ bs_raw,   // [1]
                      const float* __restrict__ nw,       // [NC,NC]
                      const float* __restrict__ gain,     // [NC]
                      const int*   __restrict__ cids,     // [D]
                      float* __restrict__ out_s,          // [T,B,D]
                      float* __restrict__ out_v)          // [T,B,D]
{
    __shared__ float Wt[NC * NC];          // Wt[j*NC + i] = sigmoid(nw[i*NC + j])
    __shared__ float g_sm[NC];
    __shared__ float partial[NGRP][NC];    // spike-count partials
    __shared__ float cf[NC];
    __shared__ float ns[NC];
    __shared__ float bm_sh, bs_sh;

    const int b   = blockIdx.x;
    const int tid = threadIdx.x;

    // ---- one-time parameter prep ----
    for (int idx = tid; idx < NC * NC; idx += TPB) {
        int i = idx / NC, j = idx % NC;    // nw row-major [i][j]
        Wt[j * NC + i] = 1.0f / (1.0f + expf(-nw[idx]));
    }
    if (tid < NC) g_sm[tid] = gain[tid];
    if (tid == 0) {
        float bm = 1.0f / (1.0f + expf(-bm_raw[0]));
        bm_sh = fminf(fmaxf(bm, 0.8f), 0.98f);
        bs_sh = 1.0f / (1.0f + expf(-bs_raw[0]));
    }

    // ---- per-thread neuron state (d = tid + k*TPB, coalesced) ----
    float v[NPT], isyn[NPT], th[NPT];
    int   cid[NPT];
    unsigned rp = 0;        // refrac packed 2 bits per neuron
    #pragma unroll
    for (int k = 0; k < NPT; k++) {
        int d = tid + k * TPB;
        v[k] = 0.0f; isyn[k] = 0.0f;
        th[k]  = fminf(fmaxf(th_raw[d], 0.05f), 0.5f);
        cid[k] = cids[d];
    }
    bool samecid = true;
    #pragma unroll
    for (int k = 1; k < NPT; k++) samecid &= (cid[k] == cid[0]);

    __syncthreads();
    const float bm = bm_sh, bs = bs_sh, om = 1.0f - bm;

    const size_t bd   = (size_t)b * DIM;
    const size_t step = (size_t)BATCH * DIM;

    for (int t = 0; t < T_STEPS; t++) {
        const float* xt = x + (size_t)t * step + bd;

        // ---- LIF update + spike ----
        unsigned smask = 0;
        #pragma unroll
        for (int k = 0; k < NPT; k++) {
            float xv = xt[tid + k * TPB];
            isyn[k] = bs * isyn[k] + xv;
            float nv = bm * v[k] + om * isyn[k];
            int refr = (rp >> (2 * k)) & 3;
            v[k] = (refr > 0) ? V_RESET : nv;
            if (v[k] >= th[k]) smask |= (1u << k);
        }

        // ---- cascade: spike counts per cluster ----
        ((float*)partial)[tid] = 0.0f;     // NGRP*NC == TPB
        __syncthreads();

        const int grp = tid >> 6;          // tid / NC
        if (samecid) {
            int cnt = __popc(smask);
            if (cnt) atomicAdd(&partial[grp][cid[0]], (float)cnt);
        } else {
            #pragma unroll
            for (int k = 0; k < NPT; k++)
                if (smask & (1u << k)) atomicAdd(&partial[grp][cid[k]], 1.0f);
        }
        __syncthreads();

        if (tid < NC) {
            float s = 0.0f;
            #pragma unroll
            for (int g = 0; g < NGRP; g++) s += partial[g][tid];
            cf[tid] = s * (1.0f / (float)(DIM / NC));   // /128 exact
        }
        __syncthreads();

        if (tid < NC) {
            float acc = 0.0f;
            #pragma unroll
            for (int j = 0; j < NC; j++) acc += cf[j] * Wt[j * NC + tid];
            ns[tid] = acc * g_sm[tid];
        }
        __syncthreads();

        // ---- apply cascade, reset, refractory, outputs ----
        float* st = out_s + (size_t)t * step + bd;
        float* vt = out_v + (size_t)t * step + bd;

        float ns0 = samecid ? ns[cid[0]] : 0.0f;
        unsigned rp_new = 0;
        #pragma unroll
        for (int k = 0; k < NPT; k++) {
            float nsk = samecid ? ns0 : ns[cid[k]];
            isyn[k] += nsk;
            float sk = (smask & (1u << k)) ? 1.0f : 0.0f;
            v[k] -= sk * th[k];
            int refr = (rp >> (2 * k)) & 3;
            int nr = (smask & (1u << k)) ? REF_T : (refr > 0 ? refr - 1 : 0);
            rp_new |= (unsigned)nr << (2 * k);
            st[tid + k * TPB] = sk;
            vt[tid + k * TPB] = v[k];
        }
        rp = rp_new;
        __syncthreads();   // protect partial/ns for next iteration
    }
}

extern "C" void kernel_launch(void* const* d_in, const int* in_sizes, int n_in,
                              void* d_out, int out_size)
{
    const float* x      = (const float*)d_in[0];   // current_in [T,B,D]
    const float* th_raw = (const float*)d_in[1];   // threshold_raw [D]
    const float* bm_raw = (const float*)d_in[2];   // beta_mem_raw [1]
    const float* bs_raw = (const float*)d_in[3];   // beta_syn_raw [1]
    const float* nw     = (const float*)d_in[4];   // neighbor_weights [NC,NC]
    const float* gain   = (const float*)d_in[5];   // cluster_gain [NC]
    const int*   cids   = (const int*)d_in[6];     // cluster_ids [D]

    float* out_s = (float*)d_out;
    float* out_v = out_s + (size_t)T_STEPS * BATCH * DIM;

    assoc_lif_kernel<<<BATCH, TPB>>>(x, th_raw, bm_raw, bs_raw, nw, gain, cids,
                                     out_s, out_v);
}

// round 6
// speedup vs baseline: 1.2708x; 1.2708x over previous
#include <cuda_runtime.h>
#include <cuda_bf16.h>
#include <math.h>

// AssociativeLIF forward: T=8, B=128, D=8192, NC=64
// d_out = [ ss (T,B,D) | vt (T,B,D) ] float32

#define T_STEPS 8
#define BATCH   128
#define DIM     8192
#define NC      64
#define TPB     1024
#define NPT     (DIM / TPB)      // 8 neurons/thread, d = tid + k*TPB
#define V_RESET (-0.1f)
#define REF_T   2

__global__ __launch_bounds__(TPB, 1)
void assoc_lif_kernel(const float* __restrict__ x,        // [T,B,D]
                      const float* __restrict__ th_raw,   // [D]
                      const float* __restrict__ bm_raw,   // [1]
                      const float* __restrict__ bs_raw,   // [1]
                      const float* __restrict__ nw,       // [NC,NC]
                      const float* __restrict__ gain,     // [NC]
                      const int*   __restrict__ cids,     // [D]
                      float* __restrict__ out_s,          // [T,B,D]
                      float* __restrict__ out_v)          // [T,B,D]
{
    __shared__ float Wts[NC * NC];      // Wts[j*64+c] = sigmoid(nw[c][j]) / 128  (exact scale)
    __shared__ float g_sm[NC];
    __shared__ float cfbuf[2][NC];      // double-buffered raw spike counts
    __shared__ float ns[NC];
    __shared__ float bm_sh, bs_sh;

    const int b   = blockIdx.x;
    const int tid = threadIdx.x;

    // ---- one-time parameter prep ----
    for (int idx = tid; idx < NC * NC; idx += TPB) {
        int c = idx >> 6, j = idx & 63;                 // nw row-major [c][j]
        Wts[j * NC + c] = (1.0f / (1.0f + expf(-nw[idx]))) * (1.0f / 128.0f);
    }
    if (tid < NC)     g_sm[tid] = gain[tid];
    if (tid < 2 * NC) ((float*)cfbuf)[tid] = 0.0f;
    if (tid == 0) {
        float bm = 1.0f / (1.0f + expf(-bm_raw[0]));
        bm_sh = fminf(fmaxf(bm, 0.8f), 0.98f);
        bs_sh = 1.0f / (1.0f + expf(-bs_raw[0]));
    }

    // fast path iff cluster_ids[d] == d % 64 for this thread's neurons
    bool okf = true;
    #pragma unroll
    for (int k = 0; k < NPT; k++)
        okf &= (cids[tid + k * TPB] == (tid & 63));
    const bool fast = (__syncthreads_and((int)okf) != 0);   // also fences smem init

    const float bm = bm_sh, bs = bs_sh, om = 1.0f - bm;

    const size_t bd   = (size_t)b * DIM;
    const size_t step = (size_t)BATCH * DIM;
    const float* xt = x     + bd;
    float*       st = out_s + bd;
    float*       vt = out_v + bd;

    // ---- state ----
    float v[NPT], isyn[NPT], xv[NPT];
    unsigned rp = 0;                    // refractory, 2 bits/neuron
    #pragma unroll
    for (int k = 0; k < NPT; k++) {
        v[k] = 0.0f; isyn[k] = 0.0f;
        xv[k] = xt[tid + k * TPB];      // preload t=0
    }

    for (int t = 0; t < T_STEPS; t++) {
        float* cf = cfbuf[t & 1];

        // ---- LIF update + spike (uses prefetched xv) ----
        unsigned smask = 0;
        #pragma unroll
        for (int k = 0; k < NPT; k++) {
            isyn[k] = bs * isyn[k] + xv[k];
            float nv = bm * v[k] + om * isyn[k];
            int refr = (rp >> (2 * k)) & 3;
            v[k] = (refr > 0) ? V_RESET : nv;
            float th = fminf(fmaxf(__ldg(&th_raw[tid + k * TPB]), 0.05f), 0.5f);
            if (v[k] >= th) smask |= (1u << k);
        }

        // ---- accumulate raw spike counts (overlaps with prefetch/stores) ----
        if (fast) {
            int cnt = __popc(smask);
            if (cnt) atomicAdd(&cf[tid & 63], (float)cnt);
        } else {
            #pragma unroll
            for (int k = 0; k < NPT; k++)
                if (smask & (1u << k)) atomicAdd(&cf[cids[tid + k * TPB]], 1.0f);
        }

        // ---- prefetch x for t+1 (hide DRAM latency behind cascade) ----
        if (t + 1 < T_STEPS) {
            const float* xn = xt + step;
            #pragma unroll
            for (int k = 0; k < NPT; k++) xv[k] = __ldg(&xn[tid + k * TPB]);
        }

        // ---- reset, refractory, outputs (independent of cascade result) ----
        unsigned rp_new = 0;
        #pragma unroll
        for (int k = 0; k < NPT; k++) {
            float sk = (smask & (1u << k)) ? 1.0f : 0.0f;
            float th = fminf(fmaxf(__ldg(&th_raw[tid + k * TPB]), 0.05f), 0.5f);
            v[k] -= sk * th;
            int refr = (rp >> (2 * k)) & 3;
            int nr = (smask & (1u << k)) ? REF_T : (refr > 0 ? refr - 1 : 0);
            rp_new |= (unsigned)nr << (2 * k);
            st[tid + k * TPB] = sk;
            vt[tid + k * TPB] = v[k];
        }
        rp = rp_new;

        __syncthreads();   // cf complete

        // ---- 64-thread: neighbor mix; zero next buffer ----
        if (tid < NC) {
            float a0 = 0.f, a1 = 0.f, a2 = 0.f, a3 = 0.f;
            #pragma unroll
            for (int j = 0; j < NC; j += 4) {
                a0 += cf[j + 0] * Wts[(j + 0) * NC + tid];
                a1 += cf[j + 1] * Wts[(j + 1) * NC + tid];
                a2 += cf[j + 2] * Wts[(j + 2) * NC + tid];
                a3 += cf[j + 3] * Wts[(j + 3) * NC + tid];
            }
            ns[tid] = ((a0 + a1) + (a2 + a3)) * g_sm[tid];
            cfbuf[(t + 1) & 1][tid] = 0.0f;    // fully consumed two syncs ago
        }

        __syncthreads();   // ns ready, next cf zeroed

        // ---- apply cascade to i_syn ----
        if (fast) {
            float a = ns[tid & 63];
            #pragma unroll
            for (int k = 0; k < NPT; k++) isyn[k] += a;
        } else {
            #pragma unroll
            for (int k = 0; k < NPT; k++) isyn[k] += ns[cids[tid + k * TPB]];
        }

        xt += step; st += step; vt += step;
    }
}

extern "C" void kernel_launch(void* const* d_in, const int* in_sizes, int n_in,
                              void* d_out, int out_size)
{
    const float* x      = (const float*)d_in[0];   // current_in [T,B,D]
    const float* th_raw = (const float*)d_in[1];   // threshold_raw [D]
    const float* bm_raw = (const float*)d_in[2];   // beta_mem_raw
    const float* bs_raw = (const float*)d_in[3];   // beta_syn_raw
    const float* nw     = (const float*)d_in[4];   // neighbor_weights [NC,NC]
    const float* gain   = (const float*)d_in[5];   // cluster_gain [NC]
    const int*   cids   = (const int*)d_in[6];     // cluster_ids [D]

    float* out_s = (float*)d_out;
    float* out_v = out_s + (size_t)T_STEPS * BATCH * DIM;

    assoc_lif_kernel<<<BATCH, TPB>>>(x, th_raw, bm_raw, bs_raw, nw, gain, cids,
                                     out_s, out_v);
}